// round 7
// baseline (speedup 1.0000x reference)
#include <cuda_runtime.h>
#include <math.h>
#include <float.h>
#include <stdint.h>

// ---------------- problem constants ----------------
#define BEAM   5
#define TOPK   5
#define VOCAB  128000
#define HIST   511
#define NUM_KV 16
#define HEADS  8
#define SEQ    2048
#define HDIM   128

#define CHUNKS   125                 // stage-1 chunks per beam
#define TPB_SM   256
#define CHUNK_F4 (VOCAB/4/CHUNKS)    // 256 float4 per chunk == TPB_SM

#define NEG_SENTINEL (-FLT_MAX)      // finite sentinel: avoids (-INF)-(-INF)=NaN in merges

#define KV_ROW_ELEMS  (HEADS*SEQ*HDIM)          // 2,097,152 floats per (kv,beam)
#define KV_ROW4       (KV_ROW_ELEMS/4)          // 524,288 float4
#define KV_TOTAL      (NUM_KV*BEAM*KV_ROW_ELEMS)

// output layout (floats), in reference tuple order
#define OFF_SAVE   (KV_TOTAL)
#define OFF_RP     (OFF_SAVE + BEAM*(HIST+1))
#define OFF_PROB   (OFF_RP + BEAM*VOCAB)
#define OFF_TOK    (OFF_PROB + BEAM)
#define OFF_MAXIDX (OFF_TOK + BEAM)

// ---------------- device scratch ----------------
__device__ float g_pm[BEAM*CHUNKS];
__device__ float g_ps[BEAM*CHUNKS];
__device__ float g_pv[BEAM*CHUNKS*TOPK];
__device__ int   g_pi[BEAM*CHUNKS*TOPK];
__device__ int   g_beam_index[BEAM];
__device__ int   g_token[BEAM];
__device__ unsigned int g_counter = 0;   // ticket for last-block combine (reset each run)

// ---------------- top-5 helpers (descending, ties -> lower index) ----------------
__device__ __forceinline__ void top5_insert(float* v, int* ix, float val, int idx) {
    if (val < v[TOPK-1]) return;
    if (val == v[TOPK-1] && idx >= ix[TOPK-1]) return;
    int p = TOPK - 1;
    #pragma unroll
    for (int q = TOPK - 1; q > 0; q--) {
        if (val > v[q-1] || (val == v[q-1] && idx < ix[q-1])) {
            v[q] = v[q-1]; ix[q] = ix[q-1]; p = q - 1;
        } else break;
    }
    v[p] = val; ix[p] = idx;
}

__device__ __forceinline__ void warp_merge(float* v, int* ix, float& m, float& s) {
    #pragma unroll
    for (int off = 16; off > 0; off >>= 1) {
        float pv[TOPK]; int pi[TOPK];
        #pragma unroll
        for (int j = 0; j < TOPK; j++) {
            pv[j] = __shfl_down_sync(0xffffffffu, v[j],  off);
            pi[j] = __shfl_down_sync(0xffffffffu, ix[j], off);
        }
        float pm = __shfl_down_sync(0xffffffffu, m, off);
        float ps = __shfl_down_sync(0xffffffffu, s, off);
        #pragma unroll
        for (int j = 0; j < TOPK; j++) top5_insert(v, ix, pv[j], pi[j]);
        float nm = fmaxf(m, pm);
        s = s * __expf(m - nm) + ps * __expf(pm - nm);   // finite sentinels, no NaN
        m = nm;
    }
}

// ---------------- kernel 1: partial logsumexp+top5, last block combines ----------------
__global__ void __launch_bounds__(TPB_SM)
softmax_topk_kernel(const float4* __restrict__ logits, const float4* __restrict__ rpen,
                    const float* __restrict__ prev_prob,
                    float* __restrict__ out_prob,
                    float* __restrict__ out_tok,
                    float* __restrict__ out_maxidx) {
    const int c = blockIdx.x;            // chunk 0..124
    const int b = blockIdx.y;            // beam
    const int t = threadIdx.x;
    const int warp = t >> 5;
    const int lane = t & 31;

    // -- phase A: one float4 of logits and rp per thread --
    const int f4i = c * CHUNK_F4 + t;
    float4 xl = __ldg(logits + (size_t)b * (VOCAB/4) + f4i);
    float4 xr = __ldg(rpen   + (size_t)b * (VOCAB/4) + f4i);
    float x[4];
    x[0] = xl.x * xr.x; x[1] = xl.y * xr.y; x[2] = xl.z * xr.z; x[3] = xl.w * xr.w;

    // -- phase B: branchless max, then sum of exp --
    float m = fmaxf(fmaxf(x[0], x[1]), fmaxf(x[2], x[3]));
    float s = __expf(x[0]-m) + __expf(x[1]-m) + __expf(x[2]-m) + __expf(x[3]-m);

    // -- phase C: per-thread top-5 (4 candidates) --
    float v[TOPK]; int ix[TOPK];
    #pragma unroll
    for (int j = 0; j < TOPK; j++) { v[j] = NEG_SENTINEL; ix[j] = 0x7FFFFFFF; }
    #pragma unroll
    for (int e = 0; e < 4; e++) top5_insert(v, ix, x[e], f4i*4 + e);

    warp_merge(v, ix, m, s);

    __shared__ float sv[8][TOPK];
    __shared__ int   si[8][TOPK];
    __shared__ float sm8[8], ss8[8];

    if (lane == 0) {
        #pragma unroll
        for (int j = 0; j < TOPK; j++) { sv[warp][j] = v[j]; si[warp][j] = ix[j]; }
        sm8[warp] = m; ss8[warp] = s;
    }
    __syncthreads();

    if (warp == 0) {
        if (lane < (TPB_SM >> 5)) {
            #pragma unroll
            for (int j = 0; j < TOPK; j++) { v[j] = sv[lane][j]; ix[j] = si[lane][j]; }
            m = sm8[lane]; s = ss8[lane];
        } else {
            #pragma unroll
            for (int j = 0; j < TOPK; j++) { v[j] = NEG_SENTINEL; ix[j] = 0x7FFFFFFF; }
            m = NEG_SENTINEL; s = 0.0f;
        }
        warp_merge(v, ix, m, s);
        if (lane == 0) {
            const int pc = b * CHUNKS + c;
            g_pm[pc] = m; g_ps[pc] = s;
            #pragma unroll
            for (int j = 0; j < TOPK; j++) {
                g_pv[pc*TOPK + j] = v[j];
                g_pi[pc*TOPK + j] = ix[j];
            }
        }
    }
    __syncthreads();

    // -- ticket: last block to finish performs the combine --
    __shared__ int s_last;
    if (t == 0) {
        __threadfence();
        unsigned int tk = atomicAdd(&g_counter, 1u);
        s_last = (tk == (unsigned)(CHUNKS*BEAM - 1));
    }
    __syncthreads();
    if (!s_last) return;

    // ================= combine (entire last block) =================
    __shared__ float s_cur[BEAM*TOPK];
    __shared__ int   s_ctok[BEAM*TOPK];

    if (warp < BEAM) {
        const int bb = warp;
        float cv[TOPK]; int cix[TOPK];
        #pragma unroll
        for (int j = 0; j < TOPK; j++) { cv[j] = NEG_SENTINEL; cix[j] = 0x7FFFFFFF; }
        float cm = NEG_SENTINEL, cs = 0.0f;
        for (int cc = lane; cc < CHUNKS; cc += 32) {
            const int pc = bb * CHUNKS + cc;
            float pm = g_pm[pc], ps = g_ps[pc];
            float nm = fmaxf(cm, pm);
            cs = cs * __expf(cm - nm) + ps * __expf(pm - nm);
            cm = nm;
            #pragma unroll
            for (int j = 0; j < TOPK; j++)
                top5_insert(cv, cix, g_pv[pc*TOPK + j], g_pi[pc*TOPK + j]);
        }
        warp_merge(cv, cix, cm, cs);
        if (lane == 0) {
            float lse = cm + logf(cs);
            float pp = prev_prob[bb];
            #pragma unroll
            for (int j = 0; j < TOPK; j++) {
                s_cur[bb*TOPK + j]  = cv[j] - lse + pp;
                s_ctok[bb*TOPK + j] = cix[j];
            }
        }
    }
    __syncthreads();

    if (t == 0) {
        bool used[BEAM*TOPK];
        #pragma unroll
        for (int i = 0; i < BEAM*TOPK; i++) used[i] = false;
        for (int k = 0; k < BEAM; k++) {
            int best = 0; float bv = -INFINITY;
            for (int i = 0; i < BEAM*TOPK; i++) {
                if (!used[i] && s_cur[i] > bv) { bv = s_cur[i]; best = i; }  // lowest idx on ties
            }
            used[best] = true;
            int bi  = best / TOPK;
            int tok = s_ctok[best];
            g_beam_index[k] = bi;
            g_token[k]      = tok;
            out_prob[k]     = bv;
            out_tok[k]      = (float)tok;
            if (k == 0) out_maxidx[0] = (float)tok;
        }
        g_counter = 0;   // reset for next graph replay (deterministic)
        __threadfence();
    }
}

// ---------------- kernel 2: fused gather keyed by SOURCE beam (explicit dedup) ----------------
struct KvPtrs { const float4* p[NUM_KV]; };

#define KV_ROWS   (NUM_KV*BEAM)          // 80 (kv, source_beam) rows
#define RP_ROWS   3                      // ceil(160000/65536)
#define RP_F4     (BEAM*VOCAB/4)         // 160000
#define TPB       256
#define XBLK      256                    // 256*256 = 65536 threads per row

__global__ void __launch_bounds__(TPB)
gather_fused_kernel(KvPtrs kp,
                    const float* __restrict__ rpen,
                    const int*   __restrict__ save_id,
                    const float* __restrict__ pen,
                    float4* __restrict__ out) {
    const int row = blockIdx.y;

    if (row < KV_ROWS) {
        // ---- KV gather, dedup by source: block = (kv, source beam si) ----
        const int kv = row / BEAM;
        const int si = row - kv * BEAM;
        const int j0 = blockIdx.x * TPB + threadIdx.x;   // 0..65535

        cudaGridDependencySynchronize();                 // PDL: results ready

        // destination mask: which new beams pull from source si
        int mask = 0;
        #pragma unroll
        for (int d = 0; d < BEAM; d++)
            if (g_beam_index[d] == si) mask |= (1 << d);
        if (mask == 0) return;                           // source unused: no traffic

        const float4* __restrict__ src = kp.p[kv] + (size_t)si * KV_ROW4;

        // read ONCE: 8 fully independent float4 loads
        float4 vals[8];
        #pragma unroll
        for (int k = 0; k < 8; k++) vals[k] = __ldcg(src + j0 + k * 65536);

        // write to every destination beam that selected this source
        #pragma unroll
        for (int d = 0; d < BEAM; d++) {
            if (mask & (1 << d)) {
                float4* __restrict__ dst = out + ((size_t)kv * BEAM + d) * KV_ROW4;
                #pragma unroll
                for (int k = 0; k < 8; k++) __stcs(dst + j0 + k * 65536, vals[k]);
            }
        }
        return;
    }

    cudaGridDependencySynchronize();                     // PDL: results ready

    if (row < KV_ROWS + RP_ROWS) {
        // ---- repeat_penalty gather (float4) + token penalty ----
        int t = (row - KV_ROWS) * 65536 + blockIdx.x * TPB + threadIdx.x;
        if (t >= RP_F4) return;
        int b  = t / (VOCAB/4);
        int v4 = t - b * (VOCAB/4);
        int bi = g_beam_index[b];
        float4 x = __ldcg((const float4*)rpen + (size_t)bi * (VOCAB/4) + v4);
        int tok = g_token[b];
        if ((tok >> 2) == v4) {
            float p = pen[0];
            ((float*)&x)[tok & 3] *= p;
        }
        float* o = (float*)out + OFF_RP;
        ((float4*)o)[t] = x;
        return;
    }

    // ---- save_id gather + token append ----
    int t = blockIdx.x * TPB + threadIdx.x;
    if (t >= BEAM * (HIST + 1)) return;
    int b = t / (HIST + 1);
    int j = t - b * (HIST + 1);
    int bi = g_beam_index[b];
    float* o = (float*)out + OFF_SAVE;
    o[t] = (j < HIST) ? (float)save_id[bi * HIST + j] : (float)g_token[b];
}

// ---------------- launch ----------------
extern "C" void kernel_launch(void* const* d_in, const int* in_sizes, int n_in,
                              void* d_out, int out_size) {
    (void)in_sizes; (void)n_in; (void)out_size;

    const int*   save_id = (const int*)  d_in[16];
    const float* rpen    = (const float*)d_in[17];
    const float* prev    = (const float*)d_in[18];
    // d_in[19] = batch_indices (arange, identity — unused)
    const float* logits  = (const float*)d_in[20];
    const float* pen     = (const float*)d_in[21];
    float* out = (float*)d_out;

    softmax_topk_kernel<<<dim3(CHUNKS, BEAM), TPB_SM>>>(
        (const float4*)logits, (const float4*)rpen, prev,
        out + OFF_PROB, out + OFF_TOK, out + OFF_MAXIDX);

    KvPtrs kp;
    for (int i = 0; i < NUM_KV; i++) kp.p[i] = (const float4*)d_in[i];

    // PDL launch: gather blocks start during softmax tail, sync before using results
    cudaLaunchConfig_t cfg = {};
    cfg.gridDim  = dim3(XBLK, KV_ROWS + RP_ROWS + 1);
    cfg.blockDim = dim3(TPB);
    cfg.stream   = 0;
    cudaLaunchAttribute attrs[1];
    attrs[0].id = cudaLaunchAttributeProgrammaticStreamSerialization;
    attrs[0].val.programmaticStreamSerializationAllowed = 1;
    cfg.attrs = attrs;
    cfg.numAttrs = 1;
    cudaLaunchKernelEx(&cfg, gather_fused_kernel, kp, rpen, save_id, pen, (float4*)out);
}

// round 8
// speedup vs baseline: 1.4757x; 1.4757x over previous
#include <cuda_runtime.h>
#include <math.h>
#include <float.h>
#include <stdint.h>

// ---------------- problem constants ----------------
#define BEAM   5
#define TOPK   5
#define VOCAB  128000
#define HIST   511
#define NUM_KV 16
#define HEADS  8
#define SEQ    2048
#define HDIM   128

#define CHUNKS   125                 // stage-1 chunks per beam
#define TPB_SM   256
#define CHUNK_F4 (VOCAB/4/CHUNKS)    // 256 float4 per chunk == TPB_SM

#define NEG_SENTINEL (-FLT_MAX)      // finite sentinel: avoids (-INF)-(-INF)=NaN in merges

#define KV_ROW_ELEMS  (HEADS*SEQ*HDIM)          // 2,097,152 floats per (kv,beam)
#define KV_ROW4       (KV_ROW_ELEMS/4)          // 524,288 float4
#define KV_TOTAL      (NUM_KV*BEAM*KV_ROW_ELEMS)

// output layout (floats), in reference tuple order
#define OFF_SAVE   (KV_TOTAL)
#define OFF_RP     (OFF_SAVE + BEAM*(HIST+1))
#define OFF_PROB   (OFF_RP + BEAM*VOCAB)
#define OFF_TOK    (OFF_PROB + BEAM)
#define OFF_MAXIDX (OFF_TOK + BEAM)

// ---------------- device scratch ----------------
__device__ float g_pm[BEAM*CHUNKS];
__device__ float g_ps[BEAM*CHUNKS];
__device__ float g_pv[BEAM*CHUNKS*TOPK];
__device__ int   g_pi[BEAM*CHUNKS*TOPK];
__device__ int   g_beam_index[BEAM];
__device__ int   g_token[BEAM];
__device__ unsigned int g_counter = 0;   // ticket for last-block combine (reset each run)

// ---------------- top-5 helpers (descending, ties -> lower index) ----------------
__device__ __forceinline__ void top5_insert(float* v, int* ix, float val, int idx) {
    if (val < v[TOPK-1]) return;
    if (val == v[TOPK-1] && idx >= ix[TOPK-1]) return;
    int p = TOPK - 1;
    #pragma unroll
    for (int q = TOPK - 1; q > 0; q--) {
        if (val > v[q-1] || (val == v[q-1] && idx < ix[q-1])) {
            v[q] = v[q-1]; ix[q] = ix[q-1]; p = q - 1;
        } else break;
    }
    v[p] = val; ix[p] = idx;
}

__device__ __forceinline__ void warp_merge(float* v, int* ix, float& m, float& s) {
    #pragma unroll
    for (int off = 16; off > 0; off >>= 1) {
        float pv[TOPK]; int pi[TOPK];
        #pragma unroll
        for (int j = 0; j < TOPK; j++) {
            pv[j] = __shfl_down_sync(0xffffffffu, v[j],  off);
            pi[j] = __shfl_down_sync(0xffffffffu, ix[j], off);
        }
        float pm = __shfl_down_sync(0xffffffffu, m, off);
        float ps = __shfl_down_sync(0xffffffffu, s, off);
        #pragma unroll
        for (int j = 0; j < TOPK; j++) top5_insert(v, ix, pv[j], pi[j]);
        float nm = fmaxf(m, pm);
        s = s * __expf(m - nm) + ps * __expf(pm - nm);   // finite sentinels, no NaN
        m = nm;
    }
}

// ---------------- kernel 1: partial logsumexp+top5, last block combines ----------------
__global__ void __launch_bounds__(TPB_SM)
softmax_topk_kernel(const float4* __restrict__ logits, const float4* __restrict__ rpen,
                    const float* __restrict__ prev_prob,
                    float* __restrict__ out_prob,
                    float* __restrict__ out_tok,
                    float* __restrict__ out_maxidx) {
    const int c = blockIdx.x;            // chunk 0..124
    const int b = blockIdx.y;            // beam
    const int t = threadIdx.x;
    const int warp = t >> 5;
    const int lane = t & 31;

    // -- phase A: one float4 of logits and rp per thread --
    const int f4i = c * CHUNK_F4 + t;
    float4 xl = __ldg(logits + (size_t)b * (VOCAB/4) + f4i);
    float4 xr = __ldg(rpen   + (size_t)b * (VOCAB/4) + f4i);
    float x[4];
    x[0] = xl.x * xr.x; x[1] = xl.y * xr.y; x[2] = xl.z * xr.z; x[3] = xl.w * xr.w;

    // -- phase B: branchless max, then sum of exp --
    float m = fmaxf(fmaxf(x[0], x[1]), fmaxf(x[2], x[3]));
    float s = __expf(x[0]-m) + __expf(x[1]-m) + __expf(x[2]-m) + __expf(x[3]-m);

    // -- phase C: per-thread top-5 (4 candidates) --
    float v[TOPK]; int ix[TOPK];
    #pragma unroll
    for (int j = 0; j < TOPK; j++) { v[j] = NEG_SENTINEL; ix[j] = 0x7FFFFFFF; }
    #pragma unroll
    for (int e = 0; e < 4; e++) top5_insert(v, ix, x[e], f4i*4 + e);

    warp_merge(v, ix, m, s);

    __shared__ float sv[8][TOPK];
    __shared__ int   si[8][TOPK];
    __shared__ float sm8[8], ss8[8];

    if (lane == 0) {
        #pragma unroll
        for (int j = 0; j < TOPK; j++) { sv[warp][j] = v[j]; si[warp][j] = ix[j]; }
        sm8[warp] = m; ss8[warp] = s;
    }
    __syncthreads();

    if (warp == 0) {
        if (lane < (TPB_SM >> 5)) {
            #pragma unroll
            for (int j = 0; j < TOPK; j++) { v[j] = sv[lane][j]; ix[j] = si[lane][j]; }
            m = sm8[lane]; s = ss8[lane];
        } else {
            #pragma unroll
            for (int j = 0; j < TOPK; j++) { v[j] = NEG_SENTINEL; ix[j] = 0x7FFFFFFF; }
            m = NEG_SENTINEL; s = 0.0f;
        }
        warp_merge(v, ix, m, s);
        if (lane == 0) {
            const int pc = b * CHUNKS + c;
            g_pm[pc] = m; g_ps[pc] = s;
            #pragma unroll
            for (int j = 0; j < TOPK; j++) {
                g_pv[pc*TOPK + j] = v[j];
                g_pi[pc*TOPK + j] = ix[j];
            }
        }
    }
    __syncthreads();

    // -- ticket: last block to finish performs the combine --
    __shared__ int s_last;
    if (t == 0) {
        __threadfence();
        unsigned int tk = atomicAdd(&g_counter, 1u);
        s_last = (tk == (unsigned)(CHUNKS*BEAM - 1));
    }
    __syncthreads();
    if (!s_last) return;

    // ================= combine (entire last block) =================
    __shared__ float s_cur[BEAM*TOPK];
    __shared__ int   s_ctok[BEAM*TOPK];

    if (warp < BEAM) {
        const int bb = warp;
        float cv[TOPK]; int cix[TOPK];
        #pragma unroll
        for (int j = 0; j < TOPK; j++) { cv[j] = NEG_SENTINEL; cix[j] = 0x7FFFFFFF; }
        float cm = NEG_SENTINEL, cs = 0.0f;
        for (int cc = lane; cc < CHUNKS; cc += 32) {
            const int pc = bb * CHUNKS + cc;
            float pm = g_pm[pc], ps = g_ps[pc];
            float nm = fmaxf(cm, pm);
            cs = cs * __expf(cm - nm) + ps * __expf(pm - nm);
            cm = nm;
            #pragma unroll
            for (int j = 0; j < TOPK; j++)
                top5_insert(cv, cix, g_pv[pc*TOPK + j], g_pi[pc*TOPK + j]);
        }
        warp_merge(cv, cix, cm, cs);
        if (lane == 0) {
            float lse = cm + logf(cs);
            float pp = prev_prob[bb];
            #pragma unroll
            for (int j = 0; j < TOPK; j++) {
                s_cur[bb*TOPK + j]  = cv[j] - lse + pp;
                s_ctok[bb*TOPK + j] = cix[j];
            }
        }
    }
    __syncthreads();

    if (t == 0) {
        bool used[BEAM*TOPK];
        #pragma unroll
        for (int i = 0; i < BEAM*TOPK; i++) used[i] = false;
        for (int k = 0; k < BEAM; k++) {
            int best = 0; float bv = -INFINITY;
            for (int i = 0; i < BEAM*TOPK; i++) {
                if (!used[i] && s_cur[i] > bv) { bv = s_cur[i]; best = i; }  // lowest idx on ties
            }
            used[best] = true;
            int bi  = best / TOPK;
            int tok = s_ctok[best];
            g_beam_index[k] = bi;
            g_token[k]      = tok;
            out_prob[k]     = bv;
            out_tok[k]      = (float)tok;
            if (k == 0) out_maxidx[0] = (float)tok;
        }
        g_counter = 0;   // reset for next graph replay (deterministic)
        __threadfence();
    }
}

// ---------------- kernel 2: gather, dest-keyed with INTERLEAVED dests ----------------
// blockIdx.x = chunk*BEAM + dest  -> the 5 dests of one (kv, chunk) are adjacent
// blocks; duplicate sources issue identical LDGs back-to-back => structural L2 dedup.
struct KvPtrs { const float4* p[NUM_KV]; };

#define TPB       256
#define XCHUNKS   256                    // 256 chunks x 256 threads = 65536 j0 slots
#define GRID_X    (XCHUNKS*BEAM)         // 1280
#define RP_F4     (BEAM*VOCAB/4)         // 160000
#define RP_BLOCKS ((RP_F4 + TPB - 1)/TPB)      // 625
#define SAVE_BLOCKS ((BEAM*(HIST+1) + TPB - 1)/TPB)  // 10

__global__ void __launch_bounds__(TPB, 8)
gather_fused_kernel(KvPtrs kp,
                    const float* __restrict__ rpen,
                    const int*   __restrict__ save_id,
                    const float* __restrict__ pen,
                    float4* __restrict__ out) {
    const int kv = blockIdx.y;

    if (kv < NUM_KV) {
        const int d     = blockIdx.x % BEAM;          // dest beam (adjacent blocks differ)
        const int chunk = blockIdx.x / BEAM;          // 0..255
        const int j0    = chunk * TPB + threadIdx.x;  // 0..65535

        cudaGridDependencySynchronize();              // PDL: beam_index ready
        const int bi = g_beam_index[d];

        const float4* __restrict__ src = kp.p[kv] + (size_t)bi * KV_ROW4;
        float4* __restrict__ dst = out + ((size_t)kv * BEAM + d) * KV_ROW4;

        #pragma unroll
        for (int h = 0; h < 2; h++) {
            float4 v0 = __ldcg(src + j0 + (4*h+0) * 65536);
            float4 v1 = __ldcg(src + j0 + (4*h+1) * 65536);
            float4 v2 = __ldcg(src + j0 + (4*h+2) * 65536);
            float4 v3 = __ldcg(src + j0 + (4*h+3) * 65536);
            __stcs(dst + j0 + (4*h+0) * 65536, v0);
            __stcs(dst + j0 + (4*h+1) * 65536, v1);
            __stcs(dst + j0 + (4*h+2) * 65536, v2);
            __stcs(dst + j0 + (4*h+3) * 65536, v3);
        }
        return;
    }

    cudaGridDependencySynchronize();                  // PDL: results ready

    if (blockIdx.x < RP_BLOCKS) {
        // ---- repeat_penalty gather (float4) + token penalty ----
        int t = blockIdx.x * TPB + threadIdx.x;
        if (t >= RP_F4) return;
        int b  = t / (VOCAB/4);
        int v4 = t - b * (VOCAB/4);
        int bi = g_beam_index[b];
        float4 x = __ldcg((const float4*)rpen + (size_t)bi * (VOCAB/4) + v4);
        int tok = g_token[b];
        if ((tok >> 2) == v4) {
            float p = pen[0];
            ((float*)&x)[tok & 3] *= p;
        }
        float* o = (float*)out + OFF_RP;
        ((float4*)o)[t] = x;
        return;
    }

    if (blockIdx.x < RP_BLOCKS + SAVE_BLOCKS) {
        // ---- save_id gather + token append ----
        int t = (blockIdx.x - RP_BLOCKS) * TPB + threadIdx.x;
        if (t >= BEAM * (HIST + 1)) return;
        int b = t / (HIST + 1);
        int j = t - b * (HIST + 1);
        int bi = g_beam_index[b];
        float* o = (float*)out + OFF_SAVE;
        o[t] = (j < HIST) ? (float)save_id[bi * HIST + j] : (float)g_token[b];
    }
}

// ---------------- launch ----------------
extern "C" void kernel_launch(void* const* d_in, const int* in_sizes, int n_in,
                              void* d_out, int out_size) {
    (void)in_sizes; (void)n_in; (void)out_size;

    const int*   save_id = (const int*)  d_in[16];
    const float* rpen    = (const float*)d_in[17];
    const float* prev    = (const float*)d_in[18];
    // d_in[19] = batch_indices (arange, identity — unused)
    const float* logits  = (const float*)d_in[20];
    const float* pen     = (const float*)d_in[21];
    float* out = (float*)d_out;

    softmax_topk_kernel<<<dim3(CHUNKS, BEAM), TPB_SM>>>(
        (const float4*)logits, (const float4*)rpen, prev,
        out + OFF_PROB, out + OFF_TOK, out + OFF_MAXIDX);

    KvPtrs kp;
    for (int i = 0; i < NUM_KV; i++) kp.p[i] = (const float4*)d_in[i];

    // PDL launch: gather blocks start during softmax tail, sync before using results
    cudaLaunchConfig_t cfg = {};
    cfg.gridDim  = dim3(GRID_X, NUM_KV + 1);
    cfg.blockDim = dim3(TPB);
    cfg.stream   = 0;
    cudaLaunchAttribute attrs[1];
    attrs[0].id = cudaLaunchAttributeProgrammaticStreamSerialization;
    attrs[0].val.programmaticStreamSerializationAllowed = 1;
    cfg.attrs = attrs;
    cfg.numAttrs = 1;
    cudaLaunchKernelEx(&cfg, gather_fused_kernel, kp, rpen, save_id, pen, (float4*)out);
}

// round 9
// speedup vs baseline: 1.5177x; 1.0284x over previous
#include <cuda_runtime.h>
#include <math.h>
#include <float.h>
#include <stdint.h>

// ---------------- problem constants ----------------
#define BEAM   5
#define TOPK   5
#define VOCAB  128000
#define HIST   511
#define NUM_KV 16
#define HEADS  8
#define SEQ    2048
#define HDIM   128

#define SM_CHUNKS 125                // stage-1 chunks per beam
#define TPB_SM    256
#define NWARPS_B  (SM_CHUNKS*8)      // 1000 warp-slots per beam (each covers 128 elems)

#define NEG_SENTINEL (-FLT_MAX)      // finite sentinel: avoids (-INF)-(-INF)=NaN in merges

#define KV_ROW_ELEMS  (HEADS*SEQ*HDIM)          // 2,097,152 floats per (kv,beam)
#define KV_ROW4       (KV_ROW_ELEMS/4)          // 524,288 float4
#define KV_TOTAL      (NUM_KV*BEAM*KV_ROW_ELEMS)

// output layout (floats), in reference tuple order
#define OFF_SAVE   (KV_TOTAL)
#define OFF_RP     (OFF_SAVE + BEAM*(HIST+1))
#define OFF_PROB   (OFF_RP + BEAM*VOCAB)
#define OFF_TOK    (OFF_PROB + BEAM)
#define OFF_MAXIDX (OFF_TOK + BEAM)

// ---------------- device scratch ----------------
__device__ float g_wm[BEAM*NWARPS_B];    // per-warp max
__device__ float g_ws[BEAM*NWARPS_B];    // per-warp sum-exp (rel. to g_wm)
__device__ int   g_beam_index[BEAM];
__device__ int   g_token[BEAM];
__device__ unsigned int g_counter = 0;   // ticket for last-block combine (reset each run)

// ---------------- top-5 helpers (descending, ties -> lower index) ----------------
__device__ __forceinline__ void top5_insert(float* v, int* ix, float val, int idx) {
    if (val < v[TOPK-1]) return;
    if (val == v[TOPK-1] && idx >= ix[TOPK-1]) return;
    int p = TOPK - 1;
    #pragma unroll
    for (int q = TOPK - 1; q > 0; q--) {
        if (val > v[q-1] || (val == v[q-1] && idx < ix[q-1])) {
            v[q] = v[q-1]; ix[q] = ix[q-1]; p = q - 1;
        } else break;
    }
    v[p] = val; ix[p] = idx;
}

__device__ __forceinline__ void warp_merge(float* v, int* ix, float& m, float& s) {
    #pragma unroll
    for (int off = 16; off > 0; off >>= 1) {
        float pv[TOPK]; int pi[TOPK];
        #pragma unroll
        for (int j = 0; j < TOPK; j++) {
            pv[j] = __shfl_down_sync(0xffffffffu, v[j],  off);
            pi[j] = __shfl_down_sync(0xffffffffu, ix[j], off);
        }
        float pm = __shfl_down_sync(0xffffffffu, m, off);
        float ps = __shfl_down_sync(0xffffffffu, s, off);
        #pragma unroll
        for (int j = 0; j < TOPK; j++) top5_insert(v, ix, pv[j], pi[j]);
        float nm = fmaxf(m, pm);
        s = s * __expf(m - nm) + ps * __expf(pm - nm);   // finite sentinels, no NaN
        m = nm;
    }
}

// ---------------- kernel 1: per-warp (max,sumexp); last block does exact top-k ----------------
// Stage 1: NO per-element top-5 tracking. Each warp covers 128 contiguous elements and
// emits (warp_max, warp_sumexp). The combine (last block) merges (m,s), picks the 5 warps
// with the largest maxes per beam (provable superset of warps holding the top-5 elements),
// and rescans just those 5*128 elements for exact top-5 values+indices.
__global__ void __launch_bounds__(TPB_SM)
softmax_topk_kernel(const float4* __restrict__ logits, const float4* __restrict__ rpen,
                    const float* __restrict__ prev_prob,
                    float* __restrict__ out_prob,
                    float* __restrict__ out_tok,
                    float* __restrict__ out_maxidx) {
    const int c = blockIdx.x;            // chunk 0..124
    const int b = blockIdx.y;            // beam
    const int t = threadIdx.x;
    const int warp = t >> 5;
    const int lane = t & 31;

    // one float4 of logits*rp per thread
    const int f4i = c * TPB_SM + t;
    float4 xl = __ldg(logits + (size_t)b * (VOCAB/4) + f4i);
    float4 xr = __ldg(rpen   + (size_t)b * (VOCAB/4) + f4i);
    float x0 = xl.x * xr.x, x1 = xl.y * xr.y, x2 = xl.z * xr.z, x3 = xl.w * xr.w;

    float m = fmaxf(fmaxf(x0, x1), fmaxf(x2, x3));
    float s = __expf(x0-m) + __expf(x1-m) + __expf(x2-m) + __expf(x3-m);

    // warp-reduce (m,s); reduced m IS the warp max
    #pragma unroll
    for (int off = 16; off > 0; off >>= 1) {
        float pm = __shfl_down_sync(0xffffffffu, m, off);
        float ps = __shfl_down_sync(0xffffffffu, s, off);
        float nm = fmaxf(m, pm);
        s = s * __expf(m - nm) + ps * __expf(pm - nm);
        m = nm;
    }
    if (lane == 0) {
        const int ws_idx = b * NWARPS_B + c * 8 + warp;   // warp-slot
        g_wm[ws_idx] = m;
        g_ws[ws_idx] = s;
        __threadfence();
    }
    __syncthreads();

    // ticket: last block combines
    __shared__ int s_last;
    if (t == 0) {
        unsigned int tk = atomicAdd(&g_counter, 1u);
        s_last = (tk == (unsigned)(SM_CHUNKS*BEAM - 1));
    }
    __syncthreads();
    if (!s_last) return;

    // ================= combine (last block; warp w handles beam w) =================
    __shared__ float s_cur[BEAM*TOPK];
    __shared__ int   s_ctok[BEAM*TOPK];

    if (warp < BEAM) {
        const int bb = warp;

        // merge 1000 per-warp (m,s) + top-5 of warp maxes
        float v[TOPK]; int ix[TOPK];
        #pragma unroll
        for (int j = 0; j < TOPK; j++) { v[j] = NEG_SENTINEL; ix[j] = 0x7FFFFFFF; }
        float cm = NEG_SENTINEL, cs = 0.0f;
        for (int i = lane; i < 1024; i += 32) {          // 32 iters, pad beyond 1000
            float pm = NEG_SENTINEL, ps = 0.0f;
            if (i < NWARPS_B) { pm = g_wm[bb*NWARPS_B + i]; ps = g_ws[bb*NWARPS_B + i]; }
            float nm = fmaxf(cm, pm);
            cs = cs * __expf(cm - nm) + ps * __expf(pm - nm);
            cm = nm;
            top5_insert(v, ix, pm, i);
        }
        warp_merge(v, ix, cm, cs);                       // lane0: beam (m,s) + top-5 slots

        float lse = cm + logf(cs);                       // valid on lane0 only
        lse = __shfl_sync(0xffffffffu, lse, 0);
        int slots[TOPK];
        #pragma unroll
        for (int j = 0; j < TOPK; j++) slots[j] = __shfl_sync(0xffffffffu, ix[j], 0);

        // rescan the 5 selected warp-slots (5*128 elements) for exact top-5
        float tv[TOPK]; int ti[TOPK];
        #pragma unroll
        for (int j = 0; j < TOPK; j++) { tv[j] = NEG_SENTINEL; ti[j] = 0x7FFFFFFF; }
        #pragma unroll
        for (int j = 0; j < TOPK; j++) {
            const int ws = slots[j];                     // 0..999, distinct
            const int f4 = ws * 32 + lane;
            float4 yl = __ldg(logits + (size_t)bb * (VOCAB/4) + f4);
            float4 yr = __ldg(rpen   + (size_t)bb * (VOCAB/4) + f4);
            const int e0 = f4 * 4;
            top5_insert(tv, ti, yl.x * yr.x, e0 + 0);
            top5_insert(tv, ti, yl.y * yr.y, e0 + 1);
            top5_insert(tv, ti, yl.z * yr.z, e0 + 2);
            top5_insert(tv, ti, yl.w * yr.w, e0 + 3);
        }
        float dm = NEG_SENTINEL, ds = 0.0f;
        warp_merge(tv, ti, dm, ds);

        if (lane == 0) {
            float pp = prev_prob[bb];
            #pragma unroll
            for (int j = 0; j < TOPK; j++) {
                s_cur[bb*TOPK + j]  = tv[j] - lse + pp;
                s_ctok[bb*TOPK + j] = ti[j];
            }
        }
    }
    __syncthreads();

    if (t == 0) {
        bool used[BEAM*TOPK];
        #pragma unroll
        for (int i = 0; i < BEAM*TOPK; i++) used[i] = false;
        for (int k = 0; k < BEAM; k++) {
            int best = 0; float bv = -INFINITY;
            for (int i = 0; i < BEAM*TOPK; i++) {
                if (!used[i] && s_cur[i] > bv) { bv = s_cur[i]; best = i; }  // lowest idx on ties
            }
            used[best] = true;
            int bi  = best / TOPK;
            int tok = s_ctok[best];
            g_beam_index[k] = bi;
            g_token[k]      = tok;
            out_prob[k]     = bv;
            out_tok[k]      = (float)tok;
            if (k == 0) out_maxidx[0] = (float)tok;
        }
        g_counter = 0;   // reset for next graph replay (deterministic)
        __threadfence();
    }
}

// ---------------- kernel 2: fused gather (exact R5 config: best measured, 180.3us) ----------------
struct KvPtrs { const float4* p[NUM_KV]; };

#define KV_ROWS   (NUM_KV*BEAM)          // 80
#define RP_ROWS   3                      // ceil(160000/65536)
#define RP_F4     (BEAM*VOCAB/4)         // 160000
#define TPB       256
#define XBLK      256                    // 256*256 = 65536 threads per row

__global__ void __launch_bounds__(TPB)
gather_fused_kernel(KvPtrs kp,
                    const float* __restrict__ rpen,
                    const int*   __restrict__ save_id,
                    const float* __restrict__ pen,
                    float4* __restrict__ out) {
    const int row = blockIdx.y;

    if (row < KV_ROWS) {
        // ---- KV copy: 8 fully independent float4 loads per thread ----
        const int kv = row / BEAM;
        const int b  = row - kv * BEAM;
        const int bi = g_beam_index[b];

        const float4* __restrict__ src = kp.p[kv] + (size_t)bi * KV_ROW4;
        float4* __restrict__ dst = out + ((size_t)kv * BEAM + b) * KV_ROW4;

        const int j0 = blockIdx.x * TPB + threadIdx.x;   // 0..65535
        float4 vals[8];
        #pragma unroll
        for (int k = 0; k < 8; k++) vals[k] = __ldcg(src + j0 + k * 65536);
        #pragma unroll
        for (int k = 0; k < 8; k++) __stcs(dst + j0 + k * 65536, vals[k]);
        return;
    }

    if (row < KV_ROWS + RP_ROWS) {
        // ---- repeat_penalty gather (float4) + token penalty ----
        int t = (row - KV_ROWS) * 65536 + blockIdx.x * TPB + threadIdx.x;
        if (t >= RP_F4) return;
        int b  = t / (VOCAB/4);
        int v4 = t - b * (VOCAB/4);
        int bi = g_beam_index[b];
        float4 x = __ldcg((const float4*)rpen + (size_t)bi * (VOCAB/4) + v4);
        int tok = g_token[b];
        if ((tok >> 2) == v4) {
            float p = pen[0];
            ((float*)&x)[tok & 3] *= p;
        }
        float* o = (float*)out + OFF_RP;
        ((float4*)o)[t] = x;
        return;
    }

    // ---- save_id gather + token append ----
    int t = blockIdx.x * TPB + threadIdx.x;
    if (t >= BEAM * (HIST + 1)) return;
    int b = t / (HIST + 1);
    int j = t - b * (HIST + 1);
    int bi = g_beam_index[b];
    float* o = (float*)out + OFF_SAVE;
    o[t] = (j < HIST) ? (float)save_id[bi * HIST + j] : (float)g_token[b];
}

// ---------------- launch ----------------
extern "C" void kernel_launch(void* const* d_in, const int* in_sizes, int n_in,
                              void* d_out, int out_size) {
    (void)in_sizes; (void)n_in; (void)out_size;

    const int*   save_id = (const int*)  d_in[16];
    const float* rpen    = (const float*)d_in[17];
    const float* prev    = (const float*)d_in[18];
    // d_in[19] = batch_indices (arange, identity — unused)
    const float* logits  = (const float*)d_in[20];
    const float* pen     = (const float*)d_in[21];
    float* out = (float*)d_out;

    softmax_topk_kernel<<<dim3(SM_CHUNKS, BEAM), TPB_SM>>>(
        (const float4*)logits, (const float4*)rpen, prev,
        out + OFF_PROB, out + OFF_TOK, out + OFF_MAXIDX);

    KvPtrs kp;
    for (int i = 0; i < NUM_KV; i++) kp.p[i] = (const float4*)d_in[i];
    dim3 grid(XBLK, KV_ROWS + RP_ROWS + 1);
    gather_fused_kernel<<<grid, TPB>>>(kp, rpen, save_id, pen, (float4*)out);
}